// round 1
// baseline (speedup 1.0000x reference)
#include <cuda_runtime.h>
#include <cuda_bf16.h>

// upfirdn2d: up=2, down=1, pad=(2,1), 4x4 FIR.
// Input  x: (16,128,128,128) f32 -> 2048 planes of 128x128
// Output  : (16,128,256,256) f32 -> 2048 planes of 256x256
//
// Derivation (per dim, 1-D taps f[0..3], true convolution on zero-inserted,
// zero-padded signal):
//   even o:  y[o] = f[3]*x[o/2-1]     + f[1]*x[o/2]
//   odd  o:  y[o] = f[2]*x[(o-1)/2]   + f[0]*x[(o+1)/2]
// 2-D output (oy,ox) = sum over the 2x2 input corner with weights
// K[ky][kx] where ky in {3,1} (even oy) or {2,0} (odd oy), same for kx.
//
// Each thread computes a 2-row x 4-col output quad anchored at (2*iy, 4*g),
// reading input rows iy-1..iy+1, cols 2g-1..2g+2 (3x4 patch).

#define H  128
#define W  128
#define OH 256
#define OW 256

__global__ __launch_bounds__(256) void fir_up2_kernel(
    const float* __restrict__ x,
    const float* __restrict__ kern,
    float* __restrict__ out)
{
    const int plane = blockIdx.z;
    const float* __restrict__ xp = x + (size_t)plane * (H * W);
    float* __restrict__ op = out + (size_t)plane * (OH * OW);

    const int g  = blockIdx.x * blockDim.x + threadIdx.x;   // 0..63  (output col quad)
    const int iy = blockIdx.y * blockDim.y + threadIdx.y;   // 0..127 (output row pair)

    // 4x4 FIR kernel -> registers (uniform across warp, L1-broadcast)
    float K[4][4];
#pragma unroll
    for (int a = 0; a < 16; a++)
        (&K[0][0])[a] = __ldg(kern + a);

    const int c0 = 2 * g;  // input column of 'n'

    float am, an, ap, aq;  // row iy-1 : cols c0-1, c0, c0+1, c0+2
    float bm, bn, bp, bq;  // row iy
    float cm, cn, cp, cq;  // row iy+1

    auto load_row = [&](int r, float& m, float& n, float& p, float& q) {
        if (r < 0 || r >= H) { m = n = p = q = 0.0f; return; }
        const float* row = xp + r * W;
        float2 np = *(const float2*)(row + c0);   // c0 even -> 8B aligned
        n = np.x;
        p = np.y;
        m = (c0 > 0)      ? __ldg(row + c0 - 1) : 0.0f;
        q = (c0 + 2 < W)  ? __ldg(row + c0 + 2) : 0.0f;
    };

    load_row(iy - 1, am, an, ap, aq);
    load_row(iy,     bm, bn, bp, bq);
    load_row(iy + 1, cm, cn, cp, cq);

    float4 o0, o1;
    // output row 2*iy   (even): row taps K[3][.] on (iy-1), K[1][.] on (iy)
    o0.x = K[3][3]*am + K[3][1]*an + K[1][3]*bm + K[1][1]*bn;  // col 4g   (even)
    o0.y = K[3][2]*an + K[3][0]*ap + K[1][2]*bn + K[1][0]*bp;  // col 4g+1 (odd)
    o0.z = K[3][3]*an + K[3][1]*ap + K[1][3]*bn + K[1][1]*bp;  // col 4g+2 (even)
    o0.w = K[3][2]*ap + K[3][0]*aq + K[1][2]*bp + K[1][0]*bq;  // col 4g+3 (odd)
    // output row 2*iy+1 (odd): row taps K[2][.] on (iy), K[0][.] on (iy+1)
    o1.x = K[2][3]*bm + K[2][1]*bn + K[0][3]*cm + K[0][1]*cn;
    o1.y = K[2][2]*bn + K[2][0]*bp + K[0][2]*cn + K[0][0]*cp;
    o1.z = K[2][3]*bn + K[2][1]*bp + K[0][3]*cn + K[0][1]*cp;
    o1.w = K[2][2]*bp + K[2][0]*bq + K[0][2]*cp + K[0][0]*cq;

    *(float4*)(op + (size_t)(2 * iy)     * OW + 4 * g) = o0;
    *(float4*)(op + (size_t)(2 * iy + 1) * OW + 4 * g) = o1;
}

extern "C" void kernel_launch(void* const* d_in, const int* in_sizes, int n_in,
                              void* d_out, int out_size) {
    const float* x = (const float*)d_in[0];
    const float* k = (const float*)d_in[1];
    float* out = (float*)d_out;

    const int planes = in_sizes[0] / (H * W);   // 2048
    dim3 block(32, 8);
    dim3 grid((W / 2) / 32, H / 8, planes);     // (2, 16, 2048)
    fir_up2_kernel<<<grid, block>>>(x, k, out);
}

// round 2
// speedup vs baseline: 1.0617x; 1.0617x over previous
#include <cuda_runtime.h>
#include <cuda_bf16.h>

// upfirdn2d: up=2, down=1, pad=(2,1), 4x4 FIR (rank-1: K = g x f).
// Input  x: 2048 planes of 128x128 f32 -> Output: 2048 planes of 256x256 f32.
//
// Per-dim taps on 1D signal (true conv over zero-inserted, padded):
//   even o: f[3]*x[o/2-1] + f[1]*x[o/2]
//   odd  o: f[2]*x[(o-1)/2] + f[0]*x[(o+1)/2]
//
// Separable plan: per input row compute horizontal half-convolution h[0..3]
// (4 output cols from input cols c0-1..c0+2), then vertical combine:
//   out row 2r   = g[3]*h(r-1) + g[1]*h(r)
//   out row 2r+1 = g[2]*h(r)   + g[0]*h(r+1)
// f[b] = K[1][b], g[a] = K[a][1]/K[1][1]  (exact for rank-1 K).
//
// Each warp owns a 64-col x 32-row strip of one plane and rolls down,
// loading each input row exactly once (float2/lane, halo via shuffles).

#define H   128
#define W   128
#define OW  256
#define STRIP 32   // input rows per warp

__global__ __launch_bounds__(256) void fir_up2_kernel(
    const float* __restrict__ x,
    const float* __restrict__ kern,
    float* __restrict__ out)
{
    const int plane = blockIdx.x;
    const int warp  = threadIdx.x >> 5;
    const int lane  = threadIdx.x & 31;
    const int half  = warp & 1;        // left/right 64-col half
    const int strip = warp >> 1;       // 0..3
    const int r0    = strip * STRIP;
    const int c0    = half * 64 + lane * 2;   // input col of v.x

    const float* __restrict__ xp = x + (size_t)plane * (H * W);
    float* __restrict__ op = out + (size_t)plane * (OW * 2 * H);

    // taps (rank-1 factorization of the 4x4 kernel)
    const float f0 = __ldg(kern + 4 + 0);
    const float f1 = __ldg(kern + 4 + 1);
    const float f2 = __ldg(kern + 4 + 2);
    const float f3 = __ldg(kern + 4 + 3);
    const float inv = 1.0f / f1;                 // 1/K[1][1]
    const float g0 = __ldg(kern + 0 * 4 + 1) * inv;
    const float g1 = 1.0f;                       // K[1][1]/K[1][1]
    const float g2 = __ldg(kern + 2 * 4 + 1) * inv;
    const float g3 = __ldg(kern + 3 * 4 + 1) * inv;

    // Load row r and horizontally convolve -> 4 output-col values.
    auto loadh = [&](int r) -> float4 {
        float4 h = make_float4(0.f, 0.f, 0.f, 0.f);
        if (r < 0 || r >= H) return h;
        const float* row = xp + r * W;
        float2 v = *(const float2*)(row + c0);
        float m = __shfl_up_sync(0xffffffffu, v.y, 1);
        if (lane == 0) m = (c0 == 0) ? 0.0f : __ldg(row + c0 - 1);
        float q = __shfl_down_sync(0xffffffffu, v.x, 1);
        if (lane == 31) q = (c0 + 2 >= W) ? 0.0f : __ldg(row + c0 + 2);
        h.x = f3 * m   + f1 * v.x;   // out col 2*c0   (even)
        h.y = f2 * v.x + f0 * v.y;   // out col 2*c0+1 (odd)
        h.z = f3 * v.x + f1 * v.y;   // out col 2*c0+2 (even)
        h.w = f2 * v.y + f0 * q;     // out col 2*c0+3 (odd)
        return h;
    };

    float4 hprev = loadh(r0 - 1);
    float4 hcur  = loadh(r0);

    const int oc = 2 * c0;   // output col base (mult of 4 -> float4 aligned)

#pragma unroll 4
    for (int i = 0; i < STRIP; i++) {
        const int r = r0 + i;
        float4 hnxt = loadh(r + 1);

        float4 e, o;
        e.x = g3 * hprev.x + g1 * hcur.x;
        e.y = g3 * hprev.y + g1 * hcur.y;
        e.z = g3 * hprev.z + g1 * hcur.z;
        e.w = g3 * hprev.w + g1 * hcur.w;
        o.x = g2 * hcur.x + g0 * hnxt.x;
        o.y = g2 * hcur.y + g0 * hnxt.y;
        o.z = g2 * hcur.z + g0 * hnxt.z;
        o.w = g2 * hcur.w + g0 * hnxt.w;

        *(float4*)(op + (size_t)(2 * r)     * OW + oc) = e;
        *(float4*)(op + (size_t)(2 * r + 1) * OW + oc) = o;

        hprev = hcur;
        hcur  = hnxt;
    }
}

extern "C" void kernel_launch(void* const* d_in, const int* in_sizes, int n_in,
                              void* d_out, int out_size) {
    const float* x = (const float*)d_in[0];
    const float* k = (const float*)d_in[1];
    float* out = (float*)d_out;

    const int planes = in_sizes[0] / (H * W);   // 2048
    fir_up2_kernel<<<planes, 256>>>(x, k, out);
}

// round 3
// speedup vs baseline: 1.1267x; 1.0612x over previous
#include <cuda_runtime.h>
#include <cuda_bf16.h>

// upfirdn2d: up=2, down=1, pad=(2,1), 4x4 separable FIR (rank-1: K = g x f).
// Input 2048 planes of 128x128 f32 -> Output 2048 planes of 256x256 f32.
//
// Per-dim half-phase taps (true conv on zero-inserted, padded signal):
//   even o: f[3]*x[o/2-1] + f[1]*x[o/2]
//   odd  o: f[2]*x[(o-1)/2] + f[0]*x[(o+1)/2]
// Horizontal half-conv per input row -> h[8] per lane, then vertical combine:
//   out row 2r   = g3*h(r-1) + h(r)          (g1 normalized to 1)
//   out row 2r+1 = g2*h(r)   + g0*h(r+1)
//
// One warp spans a FULL input row (32 lanes x float4 = 128 cols), so the
// horizontal halo is pure warp-shuffle and lanes 0/31 see the true zero pad.
// Each warp rolls down 16 rows, loading each input row exactly once.

#define H   128
#define W   128
#define OW  256
#define RPW 16   // input rows per warp

__global__ __launch_bounds__(256) void fir_up2_kernel(
    const float* __restrict__ x,
    const float* __restrict__ kern,
    float* __restrict__ out)
{
    const int plane = blockIdx.x;
    const int warp  = threadIdx.x >> 5;
    const int lane  = threadIdx.x & 31;
    const int r0    = warp * RPW;          // 8 warps x 16 rows = 128
    const int c0    = lane * 4;            // input col of v.x

    const float* __restrict__ xp = x + (size_t)plane * (H * W);
    float* __restrict__ op = out + (size_t)plane * (OW * 2 * H);

    // taps (rank-1 factorization of the 4x4 kernel)
    const float f0 = __ldg(kern + 4 + 0);
    const float f1 = __ldg(kern + 4 + 1);
    const float f2 = __ldg(kern + 4 + 2);
    const float f3 = __ldg(kern + 4 + 3);
    const float inv = 1.0f / f1;
    const float g0 = __ldg(kern + 0 * 4 + 1) * inv;
    const float g2 = __ldg(kern + 2 * 4 + 1) * inv;
    const float g3 = __ldg(kern + 3 * 4 + 1) * inv;

    // Load one full input row (LDG.128/lane) + horizontal half-conv -> h[8].
    auto loadh = [&](int r, float h[8]) {
        if (r < 0 || r >= H) {
#pragma unroll
            for (int j = 0; j < 8; j++) h[j] = 0.0f;
            return;
        }
        float4 v = __ldcs((const float4*)(xp + r * W + c0));
        float m = __shfl_up_sync(0xffffffffu, v.w, 1);
        if (lane == 0) m = 0.0f;               // true left zero-pad
        float q = __shfl_down_sync(0xffffffffu, v.x, 1);
        if (lane == 31) q = 0.0f;              // true right zero-pad
        h[0] = f3 * m   + f1 * v.x;
        h[1] = f2 * v.x + f0 * v.y;
        h[2] = f3 * v.x + f1 * v.y;
        h[3] = f2 * v.y + f0 * v.z;
        h[4] = f3 * v.y + f1 * v.z;
        h[5] = f2 * v.z + f0 * v.w;
        h[6] = f3 * v.z + f1 * v.w;
        h[7] = f2 * v.w + f0 * q;
    };

    float hprev[8], hcur[8], hnxt[8];
    loadh(r0 - 1, hprev);
    loadh(r0,     hcur);

    const int oc = 8 * lane;   // output col base (float4-aligned)

#pragma unroll 4
    for (int i = 0; i < RPW; i++) {
        const int r = r0 + i;
        loadh(r + 1, hnxt);

        float4 e0, e1, o0, o1;
        e0.x = g3 * hprev[0] + hcur[0];
        e0.y = g3 * hprev[1] + hcur[1];
        e0.z = g3 * hprev[2] + hcur[2];
        e0.w = g3 * hprev[3] + hcur[3];
        e1.x = g3 * hprev[4] + hcur[4];
        e1.y = g3 * hprev[5] + hcur[5];
        e1.z = g3 * hprev[6] + hcur[6];
        e1.w = g3 * hprev[7] + hcur[7];
        o0.x = g2 * hcur[0] + g0 * hnxt[0];
        o0.y = g2 * hcur[1] + g0 * hnxt[1];
        o0.z = g2 * hcur[2] + g0 * hnxt[2];
        o0.w = g2 * hcur[3] + g0 * hnxt[3];
        o1.x = g2 * hcur[4] + g0 * hnxt[4];
        o1.y = g2 * hcur[5] + g0 * hnxt[5];
        o1.z = g2 * hcur[6] + g0 * hnxt[6];
        o1.w = g2 * hcur[7] + g0 * hnxt[7];

        float* re = op + (size_t)(2 * r) * OW + oc;
        float* ro = op + (size_t)(2 * r + 1) * OW + oc;
        __stcs((float4*)(re),     e0);
        __stcs((float4*)(re + 4), e1);
        __stcs((float4*)(ro),     o0);
        __stcs((float4*)(ro + 4), o1);

#pragma unroll
        for (int j = 0; j < 8; j++) { hprev[j] = hcur[j]; hcur[j] = hnxt[j]; }
    }
}

extern "C" void kernel_launch(void* const* d_in, const int* in_sizes, int n_in,
                              void* d_out, int out_size) {
    const float* x = (const float*)d_in[0];
    const float* k = (const float*)d_in[1];
    float* out = (float*)d_out;

    const int planes = in_sizes[0] / (H * W);   // 2048
    fir_up2_kernel<<<planes, 256>>>(x, k, out);
}